// round 11
// baseline (speedup 1.0000x reference)
#include <cuda_runtime.h>
#include <cuda_fp16.h>
#include <cstdint>

#define NTOK   64
#define DIM    512
#define NHEAD  16
#define HDIM   32
#define NWIN   64
#define BWTOT  1024
#define SCALE  0.17677669529663687f
#define KDIM   512

__device__ __half g_xh [BWTOT * NTOK * DIM];
__device__ __half g_qkv[3 * BWTOT * NHEAD * NTOK * HDIM];
__device__ __half g_att[BWTOT * NTOK * DIM];
__device__ __half g_wq [3 * DIM * DIM];
__device__ __half g_wp [DIM * DIM];
__device__ float  g_bm [NHEAD * NWIN * NTOK * NTOK];

// ---------------------------------------------------------------------------
__device__ __forceinline__ uint32_t smem_u32(const void* p) {
    uint32_t a;
    asm("{ .reg .u64 t; cvta.to.shared.u64 t, %1; cvt.u32.u64 %0, t; }" : "=r"(a) : "l"(p));
    return a;
}
__device__ __forceinline__ void cp16(uint32_t dst, const void* src) {
    asm volatile("cp.async.cg.shared.global [%0], [%1], 16;" :: "r"(dst), "l"(src));
}
#define CP_COMMIT() asm volatile("cp.async.commit_group;" ::: "memory")
#define CP_WAIT2()  asm volatile("cp.async.wait_group 2;" ::: "memory")
#define CP_WAIT1()  asm volatile("cp.async.wait_group 1;" ::: "memory")
#define CP_WAIT0()  asm volatile("cp.async.wait_group 0;" ::: "memory")

__device__ __forceinline__ void mma_f16(float* c, const unsigned* a, const unsigned* b) {
    asm volatile(
        "mma.sync.aligned.m16n8k16.row.col.f32.f16.f16.f32 "
        "{%0,%1,%2,%3}, {%4,%5,%6,%7}, {%8,%9}, {%0,%1,%2,%3};"
        : "+f"(c[0]), "+f"(c[1]), "+f"(c[2]), "+f"(c[3])
        : "r"(a[0]), "r"(a[1]), "r"(a[2]), "r"(a[3]), "r"(b[0]), "r"(b[1]));
}
__device__ __forceinline__ void ldsm4(unsigned* r, uint32_t a) {
    asm volatile("ldmatrix.sync.aligned.m8n8.x4.shared.b16 {%0,%1,%2,%3}, [%4];"
                 : "=r"(r[0]), "=r"(r[1]), "=r"(r[2]), "=r"(r[3]) : "r"(a));
}

// ---------------------------------------------------------------------------
// Prepasses
// ---------------------------------------------------------------------------
__global__ void h_kernel(const float* __restrict__ src, __half* __restrict__ dst, int n4)
{
    const int i = blockIdx.x * blockDim.x + threadIdx.x;
    if (i < n4) {
        float4 v = ((const float4*)src)[i];
        ((__half2*)dst)[2 * i]     = __floats2half2_rn(v.x, v.y);
        ((__half2*)dst)[2 * i + 1] = __floats2half2_rn(v.z, v.w);
    }
}

__global__ void bm_kernel(const float* __restrict__ mask, const float* __restrict__ btab,
                          const int* __restrict__ ridx)
{
    const int idx = blockIdx.x * blockDim.x + threadIdx.x;
    const int rc = idx & 4095;
    const int w  = (idx >> 12) & 63;
    const int h  = idx >> 18;
    g_bm[idx] = btab[ridx[rc] * NHEAD + h] + mask[w * 4096 + rc];
}

// ---------------------------------------------------------------------------
// fp16 mma.sync GEMM: 256 threads, 8 warps (2x4 grid of 64x32 warp tiles),
// block tile 128x128, BK=64, 3-stage cp.async, ldmatrix, XOR swizzle.
// 2 CTAs/SM -> 16 warps/SM.
// ---------------------------------------------------------------------------
#define BKH 64
#define STG 3
#define STAGE_ROWS 128
#define GEMM_SMEM (STG * 2 * STAGE_ROWS * BKH * 2)   // 98304

template<int MODE>
__global__ __launch_bounds__(256, 2) void tc_gemm(
    const float* __restrict__ bias, float* __restrict__ C)
{
    extern __shared__ char smh[];
    const uint32_t sA = smem_u32(smh);
    const uint32_t sB = sA + STG * STAGE_ROWS * 128;

    const int tid  = threadIdx.x;
    const int warp = tid >> 5;
    const int lane = tid & 31;
    const int g    = lane >> 2;
    const int tg   = lane & 3;
    const int wm   = (warp >> 2) * 64;     // 0 or 64
    const int wn   = (warp & 3) * 32;      // 0,32,64,96
    const int bm = blockIdx.y, bn = blockIdx.x;

    const __half* Ap = (MODE == 0 ? g_xh : g_att) + (size_t)bm * 128 * KDIM;
    const __half* Bp = (MODE == 0 ? g_wq : g_wp) + (size_t)bn * 128 * KDIM;

    // ldmatrix lane-address components
    const int mi    = lane >> 3;
    const int l7    = lane & 7;
    const int arow  = wm + (mi & 1) * 8 + l7;   // + mt*16
    const int achk  = mi >> 1;                  // + kk*2, ^ l7
    const int brow  = wn + (mi >> 1) * 8 + l7;  // + j*16
    const int bchk  = mi & 1;

    float acc[4][4][4];
#pragma unroll
    for (int i = 0; i < 4; i++)
#pragma unroll
        for (int j = 0; j < 4; j++)
#pragma unroll
            for (int r = 0; r < 4; r++) acc[i][j][r] = 0.0f;

    // one stage = 128 rows x 8 chunks per matrix = 1024 chunks; 4/thread each
    auto issue = [&](int ks) {
        const int k0 = ks * BKH;
        const int buf = ks % STG;
#pragma unroll
        for (int t = 0; t < 4; t++) {
            const int id = tid + t * 256;
            const int r = id >> 3, c = id & 7;
            const uint32_t off = ((buf * STAGE_ROWS + r) * 8 + (c ^ (r & 7))) * 16;
            cp16(sA + off, Ap + (size_t)r * KDIM + k0 + c * 8);
            cp16(sB + off, Bp + (size_t)r * KDIM + k0 + c * 8);
        }
        CP_COMMIT();
    };

    issue(0); issue(1);
    for (int ks = 0; ks < 8; ks++) {
        if (ks < 6) { issue(ks + 2); CP_WAIT2(); }
        else if (ks == 6) { CP_WAIT1(); }
        else { CP_WAIT0(); }
        __syncthreads();

        const int bo = (ks % STG) * STAGE_ROWS;
#pragma unroll
        for (int kk = 0; kk < 4; kk++) {
            unsigned af[4][4], bf[4][2];
#pragma unroll
            for (int mt = 0; mt < 4; mt++) {
                const int r = bo + arow + mt * 16;
                ldsm4(af[mt], sA + (r * 8 + ((kk * 2 + achk) ^ l7)) * 16);
            }
#pragma unroll
            for (int j = 0; j < 2; j++) {
                const int r = bo + brow + j * 16;
                ldsm4(&bf[2 * j][0], sB + (r * 8 + ((kk * 2 + bchk) ^ l7)) * 16);
            }
#pragma unroll
            for (int mt = 0; mt < 4; mt++)
#pragma unroll
                for (int nt = 0; nt < 4; nt++)
                    mma_f16(acc[mt][nt], af[mt], bf[nt]);
        }
        __syncthreads();
    }

#pragma unroll
    for (int mt = 0; mt < 4; mt++) {
#pragma unroll
        for (int nt = 0; nt < 4; nt++) {
#pragma unroll
            for (int half = 0; half < 2; half++) {
                const int m   = bm * 128 + wm + mt * 16 + g + half * 8;
                const int col = bn * 128 + wn + nt * 8 + 2 * tg;
                const float v0 = acc[mt][nt][half * 2 + 0] + bias[col];
                const float v1 = acc[mt][nt][half * 2 + 1] + bias[col + 1];
                if (MODE == 0) {
                    const int part = col >> 9;
                    const int h    = (col >> 5) & 15;
                    const int d    = col & 31;
                    const int bw   = m >> 6;
                    const int n    = m & 63;
                    __half* dst = &g_qkv[(((size_t)part * BWTOT + bw) * NHEAD + h)
                                         * (NTOK * HDIM) + n * HDIM + d];
                    *(__half2*)dst = __floats2half2_rn(v0, v1);
                } else {
                    *(float2*)&C[(size_t)m * DIM + col] = make_float2(v0, v1);
                }
            }
        }
    }
}

// ---------------------------------------------------------------------------
// fp16 tensor-core attention: one block per (window, head), 4 warps.
// ---------------------------------------------------------------------------
__global__ __launch_bounds__(128) void attn_kernel()
{
    __shared__ __half sq[64][40], sk[64][40];
    __shared__ __half svt[32][72];
    __shared__ __half sp[64][72];

    const int tid  = threadIdx.x;
    const int warp = tid >> 5;
    const int lane = tid & 31;
    const int g    = lane >> 2;
    const int tg   = lane & 3;
    const int bw = blockIdx.x >> 4;
    const int h  = blockIdx.x & 15;

    const __half2* qp = (const __half2*)(g_qkv + ((size_t)bw * NHEAD + h) * (NTOK * HDIM));
    const __half2* kp = qp + (size_t)BWTOT * NHEAD * NTOK * HDIM / 2;
    const __half2* vp = kp + (size_t)BWTOT * NHEAD * NTOK * HDIM / 2;

    for (int i = tid; i < NTOK * HDIM / 2; i += 128) {
        const int r = i >> 4, d = (i & 15) * 2;
        float2 q2 = __half22float2(qp[i]);
        *(__half2*)&sq[r][d] = __floats2half2_rn(q2.x * SCALE, q2.y * SCALE);
        *(__half2*)&sk[r][d] = kp[i];
        __half2 v2 = vp[i];
        svt[d][r]     = __low2half(v2);
        svt[d + 1][r] = __high2half(v2);
    }
    __syncthreads();

    const int row0 = warp * 16;
    const int r1 = row0 + g, r2 = row0 + g + 8;

    float c[8][4];
#pragma unroll
    for (int nt = 0; nt < 8; nt++)
#pragma unroll
        for (int r = 0; r < 4; r++) c[nt][r] = 0.0f;

#pragma unroll
    for (int kk = 0; kk < 2; kk++) {
        const int k0 = kk * 16;
        unsigned af[4];
        af[0] = *(const unsigned*)&sq[r1][k0 + 2 * tg];
        af[1] = *(const unsigned*)&sq[r2][k0 + 2 * tg];
        af[2] = *(const unsigned*)&sq[r1][k0 + 2 * tg + 8];
        af[3] = *(const unsigned*)&sq[r2][k0 + 2 * tg + 8];
#pragma unroll
        for (int nt = 0; nt < 8; nt++) {
            unsigned bf[2];
            bf[0] = *(const unsigned*)&sk[nt * 8 + g][k0 + 2 * tg];
            bf[1] = *(const unsigned*)&sk[nt * 8 + g][k0 + 2 * tg + 8];
            mma_f16(c[nt], af, bf);
        }
    }

    const float* bmp = g_bm + ((size_t)h * NWIN + (bw & (NWIN - 1))) * 4096;
#pragma unroll
    for (int nt = 0; nt < 8; nt++) {
        const int cc = nt * 8 + 2 * tg;
        float2 b1 = *(const float2*)&bmp[r1 * 64 + cc];
        float2 b2 = *(const float2*)&bmp[r2 * 64 + cc];
        c[nt][0] += b1.x; c[nt][1] += b1.y;
        c[nt][2] += b2.x; c[nt][3] += b2.y;
    }

    float m1 = -1e30f, m2 = -1e30f;
#pragma unroll
    for (int nt = 0; nt < 8; nt++) {
        m1 = fmaxf(m1, fmaxf(c[nt][0], c[nt][1]));
        m2 = fmaxf(m2, fmaxf(c[nt][2], c[nt][3]));
    }
#pragma unroll
    for (int off = 1; off < 4; off <<= 1) {
        m1 = fmaxf(m1, __shfl_xor_sync(0xffffffffu, m1, off));
        m2 = fmaxf(m2, __shfl_xor_sync(0xffffffffu, m2, off));
    }
    float s1 = 0.0f, s2 = 0.0f;
#pragma unroll
    for (int nt = 0; nt < 8; nt++) {
        c[nt][0] = __expf(c[nt][0] - m1);
        c[nt][1] = __expf(c[nt][1] - m1);
        c[nt][2] = __expf(c[nt][2] - m2);
        c[nt][3] = __expf(c[nt][3] - m2);
        s1 += c[nt][0] + c[nt][1];
        s2 += c[nt][2] + c[nt][3];
    }
#pragma unroll
    for (int off = 1; off < 4; off <<= 1) {
        s1 += __shfl_xor_sync(0xffffffffu, s1, off);
        s2 += __shfl_xor_sync(0xffffffffu, s2, off);
    }
    const float inv1 = 1.0f / s1, inv2 = 1.0f / s2;
#pragma unroll
    for (int nt = 0; nt < 8; nt++) {
        const int cc = nt * 8 + 2 * tg;
        *(__half2*)&sp[r1][cc] = __floats2half2_rn(c[nt][0] * inv1, c[nt][1] * inv1);
        *(__half2*)&sp[r2][cc] = __floats2half2_rn(c[nt][2] * inv2, c[nt][3] * inv2);
    }
    __syncthreads();

    float o[4][4];
#pragma unroll
    for (int nt = 0; nt < 4; nt++)
#pragma unroll
        for (int r = 0; r < 4; r++) o[nt][r] = 0.0f;

#pragma unroll
    for (int kk = 0; kk < 4; kk++) {
        const int k0 = kk * 16;
        unsigned af[4];
        af[0] = *(const unsigned*)&sp[r1][k0 + 2 * tg];
        af[1] = *(const unsigned*)&sp[r2][k0 + 2 * tg];
        af[2] = *(const unsigned*)&sp[r1][k0 + 2 * tg + 8];
        af[3] = *(const unsigned*)&sp[r2][k0 + 2 * tg + 8];
#pragma unroll
        for (int nt = 0; nt < 4; nt++) {
            unsigned bf[2];
            bf[0] = *(const unsigned*)&svt[nt * 8 + g][k0 + 2 * tg];
            bf[1] = *(const unsigned*)&svt[nt * 8 + g][k0 + 2 * tg + 8];
            mma_f16(o[nt], af, bf);
        }
    }

#pragma unroll
    for (int nt = 0; nt < 4; nt++) {
        const int col = h * HDIM + nt * 8 + 2 * tg;
        *(__half2*)&g_att[((size_t)bw * NTOK + r1) * DIM + col] =
            __floats2half2_rn(o[nt][0], o[nt][1]);
        *(__half2*)&g_att[((size_t)bw * NTOK + r2) * DIM + col] =
            __floats2half2_rn(o[nt][2], o[nt][3]);
    }
}

// ---------------------------------------------------------------------------
extern "C" void kernel_launch(void* const* d_in, const int* in_sizes, int n_in,
                              void* d_out, int out_size)
{
    const float* x      = (const float*)d_in[0];
    const float* mask   = (const float*)d_in[1];
    const float* qkv_w  = (const float*)d_in[2];
    const float* qkv_b  = (const float*)d_in[3];
    const float* btab   = (const float*)d_in[4];
    const float* proj_w = (const float*)d_in[5];
    const float* proj_b = (const float*)d_in[6];
    const int*   ridx   = (const int*)d_in[7];
    float* out = (float*)d_out;

    static bool configured = false;
    if (!configured) {
        cudaFuncSetAttribute(tc_gemm<0>, cudaFuncAttributeMaxDynamicSharedMemorySize, GEMM_SMEM);
        cudaFuncSetAttribute(tc_gemm<1>, cudaFuncAttributeMaxDynamicSharedMemorySize, GEMM_SMEM);
        configured = true;
    }

    __half* wq; cudaGetSymbolAddress((void**)&wq, g_wq);
    __half* wp; cudaGetSymbolAddress((void**)&wp, g_wp);
    __half* xh; cudaGetSymbolAddress((void**)&xh, g_xh);

    h_kernel<<<(3 * DIM * DIM / 4 + 255) / 256, 256>>>(qkv_w, wq, 3 * DIM * DIM / 4);
    h_kernel<<<(DIM * DIM / 4 + 255) / 256, 256>>>(proj_w, wp, DIM * DIM / 4);
    h_kernel<<<(BWTOT * NTOK * DIM / 4 + 255) / 256, 256>>>(x, xh, BWTOT * NTOK * DIM / 4);

    tc_gemm<0><<<dim3(12, 512), 256, GEMM_SMEM>>>(qkv_b, nullptr);
    bm_kernel<<<NHEAD * NWIN * 4096 / 256, 256>>>(mask, btab, ridx);
    attn_kernel<<<BWTOT * NHEAD, 128>>>();
    tc_gemm<1><<<dim3(4, 512), 256, GEMM_SMEM>>>(proj_b, out);
}